// round 3
// baseline (speedup 1.0000x reference)
#include <cuda_runtime.h>
#include <cstdint>

// CombineEmbeddings: out[b,s,:] = (idx[b,s] >= 0) ? patch[b, idx[b,s], :]
//                                                 : word[b, s, :]
// Shapes (fixed): B=4, S=4096, P=2048, H=4096, fp32.
// Pure HBM-bound row copy: 256 MiB read + 256 MiB write, zero reuse.
// R3: 2 rows/CTA, 4x256-bit loads front-batched (deeper MC queue),
//     streaming (.cs) stores since nothing is ever re-read.

#define CE_B 4
#define CE_S 4096
#define CE_P 2048
#define CE_H 4096

__device__ __forceinline__ void ldg256(const float* p, uint32_t r[8])
{
    asm volatile(
        "ld.global.nc.L1::no_allocate.v8.b32 {%0,%1,%2,%3,%4,%5,%6,%7}, [%8];"
        : "=r"(r[0]), "=r"(r[1]), "=r"(r[2]), "=r"(r[3]),
          "=r"(r[4]), "=r"(r[5]), "=r"(r[6]), "=r"(r[7])
        : "l"(p));
}

__device__ __forceinline__ void stg256(float* p, const uint32_t r[8])
{
    asm volatile(
        "st.global.cs.v8.b32 [%0], {%1,%2,%3,%4,%5,%6,%7,%8};"
        :: "l"(p),
           "r"(r[0]), "r"(r[1]), "r"(r[2]), "r"(r[3]),
           "r"(r[4]), "r"(r[5]), "r"(r[6]), "r"(r[7])
        : "memory");
}

__global__ void __launch_bounds__(256)
combine_embeddings_kernel(const float* __restrict__ word,
                          const float* __restrict__ patch,
                          const int*   __restrict__ idx,
                          float*       __restrict__ out)
{
    // Two consecutive rows per CTA. Rows per batch (4096) is even and row0
    // is even, so both rows always share the same batch index b.
    const int row0 = blockIdx.x * 2;
    const int row1 = row0 + 1;
    const int b    = row0 >> 12;              // row / S (S = 4096)

    const int i0 = __ldg(idx + row0);
    const int i1 = __ldg(idx + row1);

    const float* __restrict__ s0 =
        (i0 >= 0) ? (patch + ((int64_t)b * CE_P + i0) * CE_H)
                  : (word  + (int64_t)row0 * CE_H);
    const float* __restrict__ s1 =
        (i1 >= 0) ? (patch + ((int64_t)b * CE_P + i1) * CE_H)
                  : (word  + (int64_t)row1 * CE_H);

    float* __restrict__ d0 = out + (int64_t)row0 * CE_H;
    float* __restrict__ d1 = out + (int64_t)row1 * CE_H;

    // Each row = 16 KB = 256 threads x 2 x 32 B. Front-batch all four
    // 256-bit loads (128 B/thread in flight) before any store binds.
    const int e = threadIdx.x * 8;            // float offset of 32 B chunk
    uint32_t a[8], c[8], g[8], h[8];
    ldg256(s0 + e,              a);
    ldg256(s0 + e + CE_H / 2,   c);
    ldg256(s1 + e,              g);
    ldg256(s1 + e + CE_H / 2,   h);
    stg256(d0 + e,              a);
    stg256(d0 + e + CE_H / 2,   c);
    stg256(d1 + e,              g);
    stg256(d1 + e + CE_H / 2,   h);
}

extern "C" void kernel_launch(void* const* d_in, const int* in_sizes, int n_in,
                              void* d_out, int out_size)
{
    const float* word  = (const float*)d_in[0];   // [B, S, H] fp32
    const float* patch = (const float*)d_in[1];   // [B, P, H] fp32
    const int*   idx   = (const int*)d_in[2];     // [B, S] int32
    float*       out   = (float*)d_out;           // [B, S, H] fp32

    const int rows = CE_B * CE_S;                 // 16384
    combine_embeddings_kernel<<<rows / 2, 256>>>(word, patch, idx, out);
}